// round 1
// baseline (speedup 1.0000x reference)
#include <cuda_runtime.h>
#include <cuda_bf16.h>
#include <mma.h>
#include <math.h>
#include <cstdint>

using namespace nvcuda;

// ---------------------------------------------------------------------------
// Problem constants
// ---------------------------------------------------------------------------
static constexpr int B_    = 4;
static constexpr int LV    = 768;
static constexpr int LE    = 64;
static constexpr int LT    = 832;    // LV + LE
static constexpr int DV    = 2048;
static constexpr int DE    = 1024;
static constexpr int H_    = 8;
static constexpr int DH_   = 256;
static constexpr int HD    = 2048;   // H_*DH_
static constexpr float SCALE_ = 0.0625f; // 1/sqrt(256)

// ---------------------------------------------------------------------------
// Scratch layout (single __device__ array; no runtime allocation)
// ---------------------------------------------------------------------------
static constexpr size_t SZ_QV = (size_t)B_*LV*HD;     // 6,291,456
static constexpr size_t SZ_QE = (size_t)B_*LE*HD;     //   524,288
static constexpr size_t SZ_Q  = (size_t)B_*H_*LT*DH_; // 6,815,744
static constexpr size_t SZ_S  = (size_t)B_*H_*LT*LT;  // 22,151,168
static constexpr size_t SZ_AO = (size_t)B_*LT*HD;     // 6,815,744

static constexpr size_t OFF_QV = 0;
static constexpr size_t OFF_KV = OFF_QV + SZ_QV;
static constexpr size_t OFF_VV = OFF_KV + SZ_QV;
static constexpr size_t OFF_QE = OFF_VV + SZ_QV;
static constexpr size_t OFF_KE = OFF_QE + SZ_QE;
static constexpr size_t OFF_VE = OFF_KE + SZ_QE;
static constexpr size_t OFF_Q  = OFF_VE + SZ_QE;
static constexpr size_t OFF_K  = OFF_Q  + SZ_Q;
static constexpr size_t OFF_V  = OFF_K  + SZ_Q;
static constexpr size_t OFF_S  = OFF_V  + SZ_Q;
static constexpr size_t OFF_AO = OFF_S  + SZ_S;
static constexpr size_t OFF_AV = OFF_AO + SZ_AO;
static constexpr size_t OFF_AE = OFF_AV + SZ_QV;
static constexpr size_t SCRATCH_TOTAL = OFF_AE + SZ_QE;

__device__ float g_scratch[SCRATCH_TOTAL];

// ---------------------------------------------------------------------------
// Generic tf32 WMMA GEMM: C = alpha * A @ B   (or A @ B^T when TB)
// Block tile 64x64, K-step 32, 128 threads (4 warps, each 32x32 via 2x2 frags).
// Requires: M%64==0, N%64==0, K%32==0, lda/ldb/ldc %4==0 (all hold here).
// Batched via blockIdx.z with (b,h) = (z/Hdiv, z%Hdiv) stride decomposition.
// ---------------------------------------------------------------------------
static constexpr int BM = 64, BN = 64, BK = 32;

template<bool TB>
__global__ __launch_bounds__(128)
void gemm_tf32(const float* __restrict__ A, const float* __restrict__ B,
               float* __restrict__ C,
               int M, int N, int K, int lda, int ldb, int ldc,
               long long sAb, long long sAh,
               long long sBb, long long sBh,
               long long sCb, long long sCh,
               int Hdiv, float alpha)
{
    {
        int z  = blockIdx.z;
        int bb = z / Hdiv;
        int hh = z - bb * Hdiv;
        A += bb * sAb + hh * sAh;
        B += bb * sBb + hh * sBh;
        C += bb * sCb + hh * sCh;
    }

    const int m0  = blockIdx.y * BM;
    const int n0  = blockIdx.x * BN;
    const int tid = threadIdx.x;

    __shared__ __align__(32) float As[BM][BK + 8];   // 64 x 40
    __shared__ __align__(32) float Bs[64 * 72];      // big enough for both layouts
    constexpr int LDBS = TB ? (BK + 8) : (BN + 8);   // 40 : 72

    wmma::fragment<wmma::accumulator, 16, 16, 8, float> acc[2][2];
#pragma unroll
    for (int i = 0; i < 2; i++)
#pragma unroll
        for (int j = 0; j < 2; j++)
            wmma::fill_fragment(acc[i][j], 0.0f);

    const int warp = tid >> 5;
    const int wm = (warp >> 1) * 32;
    const int wn = (warp & 1) * 32;

    for (int k0 = 0; k0 < K; k0 += BK) {
        // ---- load A tile 64x32 (float4, tf32-round into smem) ----
#pragma unroll
        for (int s = tid; s < 512; s += 128) {
            int r = s >> 3, c = (s & 7) << 2;
            float4 v = *reinterpret_cast<const float4*>(
                A + (size_t)(m0 + r) * lda + k0 + c);
            As[r][c + 0] = wmma::__float_to_tf32(v.x);
            As[r][c + 1] = wmma::__float_to_tf32(v.y);
            As[r][c + 2] = wmma::__float_to_tf32(v.z);
            As[r][c + 3] = wmma::__float_to_tf32(v.w);
        }
        // ---- load B tile ----
        if (!TB) {
            // B[K,N] row-major: tile 32(k) x 64(n)
#pragma unroll
            for (int s = tid; s < 512; s += 128) {
                int r = s >> 4, c = (s & 15) << 2;
                float4 v = *reinterpret_cast<const float4*>(
                    B + (size_t)(k0 + r) * ldb + n0 + c);
                Bs[r * LDBS + c + 0] = wmma::__float_to_tf32(v.x);
                Bs[r * LDBS + c + 1] = wmma::__float_to_tf32(v.y);
                Bs[r * LDBS + c + 2] = wmma::__float_to_tf32(v.z);
                Bs[r * LDBS + c + 3] = wmma::__float_to_tf32(v.w);
            }
        } else {
            // B[N,K] row-major (B^T math): tile 64(n) x 32(k)
#pragma unroll
            for (int s = tid; s < 512; s += 128) {
                int r = s >> 3, c = (s & 7) << 2;
                float4 v = *reinterpret_cast<const float4*>(
                    B + (size_t)(n0 + r) * ldb + k0 + c);
                Bs[r * LDBS + c + 0] = wmma::__float_to_tf32(v.x);
                Bs[r * LDBS + c + 1] = wmma::__float_to_tf32(v.y);
                Bs[r * LDBS + c + 2] = wmma::__float_to_tf32(v.z);
                Bs[r * LDBS + c + 3] = wmma::__float_to_tf32(v.w);
            }
        }
        __syncthreads();

#pragma unroll
        for (int kk = 0; kk < BK; kk += 8) {
            wmma::fragment<wmma::matrix_a, 16, 16, 8, wmma::precision::tf32,
                           wmma::row_major> af[2];
            wmma::load_matrix_sync(af[0], &As[wm][kk], BK + 8);
            wmma::load_matrix_sync(af[1], &As[wm + 16][kk], BK + 8);
            if (!TB) {
                wmma::fragment<wmma::matrix_b, 16, 16, 8, wmma::precision::tf32,
                               wmma::row_major> bf[2];
                wmma::load_matrix_sync(bf[0], &Bs[kk * LDBS + wn], LDBS);
                wmma::load_matrix_sync(bf[1], &Bs[kk * LDBS + wn + 16], LDBS);
#pragma unroll
                for (int i = 0; i < 2; i++)
#pragma unroll
                    for (int j = 0; j < 2; j++)
                        wmma::mma_sync(acc[i][j], af[i], bf[j], acc[i][j]);
            } else {
                wmma::fragment<wmma::matrix_b, 16, 16, 8, wmma::precision::tf32,
                               wmma::col_major> bf[2];
                wmma::load_matrix_sync(bf[0], &Bs[(wn) * LDBS + kk], LDBS);
                wmma::load_matrix_sync(bf[1], &Bs[(wn + 16) * LDBS + kk], LDBS);
#pragma unroll
                for (int i = 0; i < 2; i++)
#pragma unroll
                    for (int j = 0; j < 2; j++)
                        wmma::mma_sync(acc[i][j], af[i], bf[j], acc[i][j]);
            }
        }
        __syncthreads();
    }

#pragma unroll
    for (int i = 0; i < 2; i++)
#pragma unroll
        for (int j = 0; j < 2; j++) {
#pragma unroll
            for (int t = 0; t < acc[i][j].num_elements; t++)
                acc[i][j].x[t] *= alpha;
            wmma::store_matrix_sync(
                C + (size_t)(m0 + wm + 16 * i) * ldc + n0 + wn + 16 * j,
                acc[i][j], ldc, wmma::mem_row_major);
        }
}

// ---------------------------------------------------------------------------
// Gather projected QKV into [B,H,LT,DH] layout + apply RoPE to Q,K
// one thread per (b,h,l,i), i in [0,128): handles the rotated pair (i, i+128)
// ---------------------------------------------------------------------------
__global__ void assemble_rope(const float* __restrict__ Qv, const float* __restrict__ Kv,
                              const float* __restrict__ Vv,
                              const float* __restrict__ Qe, const float* __restrict__ Ke,
                              const float* __restrict__ Ve,
                              const int* __restrict__ pos_ids,
                              float* __restrict__ Q, float* __restrict__ K,
                              float* __restrict__ V)
{
    int idx = blockIdx.x * blockDim.x + threadIdx.x;
    const int TOTAL = B_ * H_ * LT * (DH_ / 2);
    if (idx >= TOTAL) return;

    int i = idx & 127;
    int t = idx >> 7;
    int l = t % LT;  t /= LT;
    int h = t % H_;
    int b = t / H_;

    int pos = pos_ids[b * LT + l];
    // inv_freq = ROPE_BASE^(-2i/DH) = exp(-ln(1e4) * i / 128)
    const float LN_BASE_OVER_128 = 9.210340371976184f / 128.0f;
    float ang = (float)pos * expf(-LN_BASE_OVER_128 * (float)i);
    float cs = cosf(ang), sn = sinf(ang);

    const float *sq, *sk, *sv;
    size_t row;
    if (l < LV) { row = (size_t)(b * LV + l); sq = Qv; sk = Kv; sv = Vv; }
    else        { row = (size_t)(b * LE + (l - LV)); sq = Qe; sk = Ke; sv = Ve; }
    size_t src = row * HD + h * DH_ + i;

    size_t dst = (((size_t)(b * H_ + h) * LT) + l) * DH_ + i;

    float q1 = sq[src], q2 = sq[src + 128];
    Q[dst]       = q1 * cs - q2 * sn;
    Q[dst + 128] = q2 * cs + q1 * sn;

    float k1 = sk[src], k2 = sk[src + 128];
    K[dst]       = k1 * cs - k2 * sn;
    K[dst + 128] = k2 * cs + k1 * sn;

    V[dst]       = sv[src];
    V[dst + 128] = sv[src + 128];
}

// ---------------------------------------------------------------------------
// Row softmax over LT=832, with additive mask [B,1,LT,LT]. In place.
// One block (256 thr) per row; row = (b*H + h)*LT + q
// ---------------------------------------------------------------------------
__global__ void softmax_rows(float* __restrict__ S, const float* __restrict__ mask)
{
    int row = blockIdx.x;
    int z = row / LT, q = row - z * LT;
    int b = z / H_;
    const float* mrow = mask + ((size_t)b * LT + q) * LT;
    float* srow = S + (size_t)row * LT;

    __shared__ float red[256];
    int tid = threadIdx.x;

    float m = -1e30f;
    for (int k = tid; k < LT; k += 256) {
        float v = srow[k] + mrow[k];
        srow[k] = v;
        m = fmaxf(m, v);
    }
    red[tid] = m; __syncthreads();
    for (int s = 128; s > 0; s >>= 1) {
        if (tid < s) red[tid] = fmaxf(red[tid], red[tid + s]);
        __syncthreads();
    }
    m = red[0]; __syncthreads();

    float sum = 0.0f;
    for (int k = tid; k < LT; k += 256) {
        float e = __expf(srow[k] - m);
        srow[k] = e;
        sum += e;
    }
    red[tid] = sum; __syncthreads();
    for (int s = 128; s > 0; s >>= 1) {
        if (tid < s) red[tid] += red[tid + s];
        __syncthreads();
    }
    float inv = 1.0f / red[0];
    for (int k = tid; k < LT; k += 256) srow[k] *= inv;
}

// ---------------------------------------------------------------------------
// Split attn_out [B, LT, HD] into vlm rows [B*LV, HD] and exp rows [B*LE, HD]
// ---------------------------------------------------------------------------
__global__ void split_attn(const float* __restrict__ AO,
                           float* __restrict__ AVb, float* __restrict__ AEb)
{
    size_t idx = (size_t)blockIdx.x * blockDim.x + threadIdx.x;
    const size_t TOTAL = (size_t)B_ * LT * HD;
    if (idx >= TOTAL) return;
    int c = (int)(idx & (HD - 1));
    int t = (int)(idx >> 11);
    int l = t % LT, b = t / LT;
    float v = AO[idx];
    if (l < LV) AVb[((size_t)(b * LV + l) << 11) + c] = v;
    else        AEb[((size_t)(b * LE + (l - LV)) << 11) + c] = v;
}

// ---------------------------------------------------------------------------
// Host side
// ---------------------------------------------------------------------------
extern "C" void kernel_launch(void* const* d_in, const int* in_sizes, int n_in,
                              void* d_out, int out_size)
{
    const float* vlm_hidden = (const float*)d_in[0];
    const float* exp_hidden = (const float*)d_in[1];
    const float* attn_mask  = (const float*)d_in[2];
    const int*   pos_ids    = (const int*)  d_in[3];
    const float* wq_v = (const float*)d_in[4];
    const float* wk_v = (const float*)d_in[5];
    const float* wv_v = (const float*)d_in[6];
    const float* wo_v = (const float*)d_in[7];
    const float* wq_e = (const float*)d_in[8];
    const float* wk_e = (const float*)d_in[9];
    const float* wv_e = (const float*)d_in[10];
    const float* wo_e = (const float*)d_in[11];
    float* out = (float*)d_out;

    float* sc = nullptr;
    cudaGetSymbolAddress((void**)&sc, g_scratch);

    float* Qv = sc + OFF_QV; float* Kv = sc + OFF_KV; float* Vv = sc + OFF_VV;
    float* Qe = sc + OFF_QE; float* Ke = sc + OFF_KE; float* Ve = sc + OFF_VE;
    float* Q  = sc + OFF_Q;  float* K  = sc + OFF_K;  float* V  = sc + OFF_V;
    float* S  = sc + OFF_S;
    float* AO = sc + OFF_AO; float* AVb = sc + OFF_AV; float* AEb = sc + OFF_AE;

    const int MV = B_ * LV;   // 3072
    const int ME = B_ * LE;   // 256

    // ---- QKV projections (vlm: M=3072,K=2048; exp: M=256,K=1024; N=2048) ----
    {
        dim3 g(HD / BN, MV / BM, 1);
        gemm_tf32<false><<<g, 128>>>(vlm_hidden, wq_v, Qv, MV, HD, DV,
                                     DV, HD, HD, 0,0,0,0,0,0, 1, 1.0f);
        gemm_tf32<false><<<g, 128>>>(vlm_hidden, wk_v, Kv, MV, HD, DV,
                                     DV, HD, HD, 0,0,0,0,0,0, 1, 1.0f);
        gemm_tf32<false><<<g, 128>>>(vlm_hidden, wv_v, Vv, MV, HD, DV,
                                     DV, HD, HD, 0,0,0,0,0,0, 1, 1.0f);
    }
    {
        dim3 g(HD / BN, ME / BM, 1);
        gemm_tf32<false><<<g, 128>>>(exp_hidden, wq_e, Qe, ME, HD, DE,
                                     DE, HD, HD, 0,0,0,0,0,0, 1, 1.0f);
        gemm_tf32<false><<<g, 128>>>(exp_hidden, wk_e, Ke, ME, HD, DE,
                                     DE, HD, HD, 0,0,0,0,0,0, 1, 1.0f);
        gemm_tf32<false><<<g, 128>>>(exp_hidden, wv_e, Ve, ME, HD, DE,
                                     DE, HD, HD, 0,0,0,0,0,0, 1, 1.0f);
    }

    // ---- gather + RoPE into [B,H,LT,DH] ----
    {
        int total = B_ * H_ * LT * (DH_ / 2);
        assemble_rope<<<(total + 255) / 256, 256>>>(Qv, Kv, Vv, Qe, Ke, Ve,
                                                    pos_ids, Q, K, V);
    }

    // ---- scores = scale * Q @ K^T, batched over 32 (b,h) ----
    {
        long long sH = (long long)LT * DH_;           // per-head stride in Q/K
        long long sB = (long long)H_ * LT * DH_;
        long long cH = (long long)LT * LT;
        long long cB = (long long)H_ * LT * LT;
        dim3 g(LT / BN, LT / BM, B_ * H_);
        gemm_tf32<true><<<g, 128>>>(Q, K, S, LT, LT, DH_,
                                    DH_, DH_, LT,
                                    sB, sH, sB, sH, cB, cH, H_, SCALE_);
    }

    // ---- softmax (+mask) in place ----
    softmax_rows<<<B_ * H_ * LT, 256>>>(S, attn_mask);

    // ---- attn_out = P @ V, written directly into [B, LT, H*DH] layout ----
    {
        long long aH = (long long)LT * LT;
        long long aB = (long long)H_ * LT * LT;
        long long bH = (long long)LT * DH_;
        long long bB = (long long)H_ * LT * DH_;
        long long cB = (long long)LT * HD;            // per-b
        long long cH = (long long)DH_;                // per-h column offset
        dim3 g(DH_ / BN, LT / BM, B_ * H_);
        gemm_tf32<false><<<g, 128>>>(S, V, AO, LT, DH_, LT,
                                     LT, DH_, HD,
                                     aB, aH, bB, bH, cB, cH, H_, 1.0f);
    }

    // ---- split into contiguous vlm / exp row blocks ----
    {
        size_t total = (size_t)B_ * LT * HD;
        split_attn<<<(unsigned)((total + 255) / 256), 256>>>(AO, AVb, AEb);
    }

    // ---- output projections straight into d_out ----
    {
        dim3 g(DV / BN, MV / BM, 1);
        gemm_tf32<false><<<g, 128>>>(AVb, wo_v, out, MV, DV, HD,
                                     HD, DV, DV, 0,0,0,0,0,0, 1, 1.0f);
    }
    {
        float* out_e = out + (size_t)MV * DV;         // 6,291,456
        dim3 g(DE / BN, ME / BM, 1);
        gemm_tf32<false><<<g, 128>>>(AEb, wo_e, out_e, ME, DE, HD,
                                     HD, DE, DE, 0,0,0,0,0,0, 1, 1.0f);
    }
}